// round 1
// baseline (speedup 1.0000x reference)
#include <cuda_runtime.h>
#include <cstdint>

#define TT 8192
#define DD 2048
#define NCH 128
#define CL (TT/NCH)   // 64

// ---------------- scratch (device globals; no allocations) ----------------
__device__ float g_xy[(size_t)TT*DD];   // ln1 out, later ln2 out
__device__ float g_mix[(size_t)TT*DD];  // lerp output (GEMM A operand)
__device__ float g_k[(size_t)TT*DD];
__device__ float g_v[(size_t)TT*DD];
__device__ float g_r[(size_t)TT*DD];    // r, later rf
__device__ float g_t0[(size_t)TT*DD];   // wkv*r, later kf^2
__device__ float g_rz[(size_t)TT*DD];
__device__ float g_w[(size_t)7*DD*DD];  // tf32-rounded weights
__device__ float g_sa[NCH*DD], g_sb[NCH*DD], g_sp[NCH*DD];   // local chunk states
__device__ float g_pa[NCH*DD], g_pb[NCH*DD], g_pp[NCH*DD];   // exclusive prefix states

// ---------------- helpers ----------------
__device__ __forceinline__ float rnd_tf32(float x) {
    uint32_t y;
    asm("cvt.rna.tf32.f32 %0, %1;" : "=r"(y) : "f"(x));
    return __uint_as_float(y);
}

__device__ __forceinline__ uint32_t saddr(const void* p) {
    return (uint32_t)__cvta_generic_to_shared(p);
}

__device__ __forceinline__ void cp_async16(uint32_t s, const void* g) {
    asm volatile("cp.async.cg.shared.global [%0], [%1], 16;" :: "r"(s), "l"(g));
}
__device__ __forceinline__ void cp_commit() {
    asm volatile("cp.async.commit_group;");
}
__device__ __forceinline__ void cp_wait1() {
    asm volatile("cp.async.wait_group 1;");
}

__device__ __forceinline__ void mma8(float d[4], const uint32_t a[4], const uint32_t b[2]) {
    asm volatile(
        "mma.sync.aligned.m16n8k8.row.col.f32.tf32.tf32.f32 "
        "{%0,%1,%2,%3}, {%4,%5,%6,%7}, {%8,%9}, {%0,%1,%2,%3};"
        : "+f"(d[0]), "+f"(d[1]), "+f"(d[2]), "+f"(d[3])
        : "r"(a[0]), "r"(a[1]), "r"(a[2]), "r"(a[3]), "r"(b[0]), "r"(b[1]));
}

// ---------------- elementwise kernels ----------------
__global__ __launch_bounds__(256) void round_kernel(const float4* __restrict__ in,
                                                    float4* __restrict__ out, int n4) {
    int i = blockIdx.x * 256 + threadIdx.x;
    if (i < n4) {
        float4 v = in[i];
        v.x = rnd_tf32(v.x); v.y = rnd_tf32(v.y); v.z = rnd_tf32(v.z); v.w = rnd_tf32(v.w);
        out[i] = v;
    }
}

__global__ __launch_bounds__(256) void ln_kernel(const float* __restrict__ x,
                                                 const float* __restrict__ gw,
                                                 const float* __restrict__ gb,
                                                 float* __restrict__ out) {
    int t = blockIdx.x;
    const float4* row = reinterpret_cast<const float4*>(x + (size_t)t * DD);
    float4 va[2];
    float s = 0.f, s2 = 0.f;
#pragma unroll
    for (int i = 0; i < 2; i++) {
        float4 v = row[threadIdx.x + i * 256];
        va[i] = v;
        s  += v.x + v.y + v.z + v.w;
        s2 += v.x*v.x + v.y*v.y + v.z*v.z + v.w*v.w;
    }
#pragma unroll
    for (int o = 16; o; o >>= 1) {
        s  += __shfl_xor_sync(0xffffffffu, s,  o);
        s2 += __shfl_xor_sync(0xffffffffu, s2, o);
    }
    __shared__ float ws[8], ws2[8];
    int wid = threadIdx.x >> 5, lane = threadIdx.x & 31;
    if (!lane) { ws[wid] = s; ws2[wid] = s2; }
    __syncthreads();
    float S = 0.f, S2 = 0.f;
#pragma unroll
    for (int i = 0; i < 8; i++) { S += ws[i]; S2 += ws2[i]; }
    float m = S * (1.0f / DD);
    float var = S2 * (1.0f / DD) - m * m;
    float inv = rsqrtf(var + 1e-5f);
    const float4* g4 = reinterpret_cast<const float4*>(gw);
    const float4* b4 = reinterpret_cast<const float4*>(gb);
    float4* o4 = reinterpret_cast<float4*>(out + (size_t)t * DD);
#pragma unroll
    for (int i = 0; i < 2; i++) {
        int c = threadIdx.x + i * 256;
        float4 v = va[i], g = g4[c], b = b4[c], o;
        o.x = (v.x - m) * inv * g.x + b.x;
        o.y = (v.y - m) * inv * g.y + b.y;
        o.z = (v.z - m) * inv * g.z + b.z;
        o.w = (v.w - m) * inv * g.w + b.w;
        o4[c] = o;
    }
}

// out = rnd_tf32( lerp(src[t-1 mod T], src[t], mix) )
__global__ __launch_bounds__(256) void mix_kernel(const float4* __restrict__ src,
                                                  const float* __restrict__ mix,
                                                  float4* __restrict__ out) {
    int idx = blockIdx.x * 256 + threadIdx.x;  // [0, T*D/4)
    const int DC = DD / 4;
    int t = idx / DC;
    int c = idx - t * DC;
    int tp = (t == 0) ? (TT - 1) : (t - 1);
    float4 a = src[(size_t)tp * DC + c];
    float4 b = src[idx];
    float4 m = reinterpret_cast<const float4*>(mix)[c];
    float4 o;
    o.x = rnd_tf32(a.x + m.x * (b.x - a.x));
    o.y = rnd_tf32(a.y + m.y * (b.y - a.y));
    o.z = rnd_tf32(a.z + m.z * (b.z - a.z));
    o.w = rnd_tf32(a.w + m.w * (b.w - a.w));
    out[idx] = o;
}

// ---------------- WKV chunked scan ----------------
__global__ __launch_bounds__(256) void wkv_phase1(const float* __restrict__ k,
                                                  const float* __restrict__ v,
                                                  const float* __restrict__ td) {
    int c = blockIdx.x * 256 + threadIdx.x;
    int ch = blockIdx.y;
    float w = -__expf(td[c]);
    float aa = 0.f, bb = 0.f, pp = -1e38f;
    size_t base = (size_t)ch * CL * DD + c;
    for (int i = 0; i < CL; i++) {
        float kt = k[base + (size_t)i * DD];
        float vt = v[base + (size_t)i * DD];
        float ww2 = pp + w;
        float p2 = fmaxf(ww2, kt);
        float e1 = __expf(ww2 - p2), e2 = __expf(kt - p2);
        aa = e1 * aa + e2 * vt;
        bb = e1 * bb + e2;
        pp = p2;
    }
    int idx = ch * DD + c;
    g_sa[idx] = aa; g_sb[idx] = bb; g_sp[idx] = pp;
}

__global__ __launch_bounds__(256) void wkv_phase2(const float* __restrict__ td) {
    int c = blockIdx.x * 256 + threadIdx.x;
    float w = -__expf(td[c]);
    float clw = (float)CL * w;
    float aa = 0.f, bb = 0.f, pp = -1e38f;
    for (int ch = 0; ch < NCH; ch++) {
        int idx = ch * DD + c;
        g_pa[idx] = aa; g_pb[idx] = bb; g_pp[idx] = pp;
        float pd = pp + clw;
        float la = g_sa[idx], lb = g_sb[idx], lp = g_sp[idx];
        float p = fmaxf(pd, lp);
        float e1 = __expf(pd - p), e2 = __expf(lp - p);
        aa = e1 * aa + e2 * la;
        bb = e1 * bb + e2 * lb;
        pp = p;
    }
}

__global__ __launch_bounds__(256) void wkv_phase3(const float* __restrict__ k,
                                                  const float* __restrict__ v,
                                                  const float* __restrict__ r,
                                                  const float* __restrict__ tf,
                                                  const float* __restrict__ td,
                                                  float* __restrict__ out) {
    int c = blockIdx.x * 256 + threadIdx.x;
    int ch = blockIdx.y;
    float w = -__expf(td[c]);
    float u = tf[c];
    int idx = ch * DD + c;
    float aa = g_pa[idx], bb = g_pb[idx], pp = g_pp[idx];
    size_t base = (size_t)ch * CL * DD + c;
    for (int i = 0; i < CL; i++) {
        size_t off = base + (size_t)i * DD;
        float kt = k[off], vt = v[off];
        float ww = u + kt;
        float p = fmaxf(pp, ww);
        float e1 = __expf(pp - p), e2 = __expf(ww - p);
        float o = (e1 * aa + e2 * vt) / (e1 * bb + e2);
        out[off] = rnd_tf32(o * r[off]);
        float ww2 = pp + w;
        float p2 = fmaxf(ww2, kt);
        e1 = __expf(ww2 - p2); e2 = __expf(kt - p2);
        aa = e1 * aa + e2 * vt;
        bb = e1 * bb + e2;
        pp = p2;
    }
}

// ---------------- TF32 GEMM: out[t,j] = epi( sum_i A[t,i]*W[j,i] + bias[j] ) ----------------
// MODE 0: plain   1: sigmoid   2: rnd(relu^2)   3: +aux1   4: *aux1 + aux2
#define BM 128
#define BN 128
#define BK 16
#define KT_ITERS (DD / BK)

template <int MODE>
__device__ __forceinline__ float epi(float v, size_t idx,
                                     const float* __restrict__ a1,
                                     const float* __restrict__ a2) {
    if (MODE == 1) return 1.0f / (1.0f + expf(-v));
    if (MODE == 2) { float t = v > 0.f ? v : 0.f; return rnd_tf32(t * t); }
    if (MODE == 3) return v + a1[idx];
    if (MODE == 4) return v * a1[idx] + a2[idx];
    return v;
}

template <int MODE>
__global__ __launch_bounds__(256, 2) void gemm_kernel(
    const float* __restrict__ A, const float* __restrict__ W,
    const float* __restrict__ bias,
    const float* __restrict__ aux1, const float* __restrict__ aux2,
    float* __restrict__ out) {
    __shared__ float As[2][BM][20];
    __shared__ float Bs[2][BN][20];

    int bm = blockIdx.x * BM;
    int bn = blockIdx.y * BN;
    int tid = threadIdx.x;
    int warp = tid >> 5, lane = tid & 31;
    int wm = (warp >> 2) * 64;   // 2 warps over M
    int wn = (warp & 3) * 32;    // 4 warps over N

    const float* Ab = A + (size_t)bm * DD;
    const float* Wb = W + (size_t)bn * DD;

    float acc[4][4][4];
#pragma unroll
    for (int i = 0; i < 4; i++)
#pragma unroll
        for (int j = 0; j < 4; j++)
#pragma unroll
            for (int q = 0; q < 4; q++) acc[i][j][q] = 0.f;

    auto load_stage = [&](int kk, int s) {
#pragma unroll
        for (int i = 0; i < 2; i++) {
            int c = tid + i * 256;
            int row = c >> 2;
            int col4 = (c & 3) * 4;
            cp_async16(saddr(&As[s][row][col4]), Ab + (size_t)row * DD + kk + col4);
            cp_async16(saddr(&Bs[s][row][col4]), Wb + (size_t)row * DD + kk + col4);
        }
    };

    load_stage(0, 0);
    cp_commit();

    for (int kt = 0; kt < KT_ITERS; kt++) {
        int s = kt & 1;
        if (kt + 1 < KT_ITERS) load_stage((kt + 1) * BK, s ^ 1);
        cp_commit();
        cp_wait1();
        __syncthreads();

#pragma unroll
        for (int ks = 0; ks < 2; ks++) {
            int col0 = ks * 8 + (lane & 3);
            int arow = wm + (lane >> 2);
            uint32_t af[4][4];
#pragma unroll
            for (int mi = 0; mi < 4; mi++) {
                af[mi][0] = __float_as_uint(As[s][arow + mi * 16][col0]);
                af[mi][1] = __float_as_uint(As[s][arow + mi * 16 + 8][col0]);
                af[mi][2] = __float_as_uint(As[s][arow + mi * 16][col0 + 4]);
                af[mi][3] = __float_as_uint(As[s][arow + mi * 16 + 8][col0 + 4]);
            }
            int brow = wn + (lane >> 2);
            uint32_t bf[4][2];
#pragma unroll
            for (int ni = 0; ni < 4; ni++) {
                bf[ni][0] = __float_as_uint(Bs[s][brow + ni * 8][col0]);
                bf[ni][1] = __float_as_uint(Bs[s][brow + ni * 8][col0 + 4]);
            }
#pragma unroll
            for (int mi = 0; mi < 4; mi++)
#pragma unroll
                for (int ni = 0; ni < 4; ni++)
                    mma8(acc[mi][ni], af[mi], bf[ni]);
        }
        __syncthreads();
    }

    // epilogue
#pragma unroll
    for (int mi = 0; mi < 4; mi++) {
        int r0 = bm + wm + mi * 16 + (lane >> 2);
#pragma unroll
        for (int ni = 0; ni < 4; ni++) {
            int c0 = bn + wn + ni * 8 + (lane & 3) * 2;
            float b0 = bias[c0], b1 = bias[c0 + 1];
            size_t i0 = (size_t)r0 * DD + c0;
            size_t i1 = (size_t)(r0 + 8) * DD + c0;
            out[i0]     = epi<MODE>(acc[mi][ni][0] + b0, i0,     aux1, aux2);
            out[i0 + 1] = epi<MODE>(acc[mi][ni][1] + b1, i0 + 1, aux1, aux2);
            out[i1]     = epi<MODE>(acc[mi][ni][2] + b0, i1,     aux1, aux2);
            out[i1 + 1] = epi<MODE>(acc[mi][ni][3] + b1, i1 + 1, aux1, aux2);
        }
    }
}

// ---------------- host orchestration ----------------
extern "C" void kernel_launch(void* const* d_in, const int* in_sizes, int n_in,
                              void* d_out, int out_size) {
    const float* x = (const float*)d_in[0];
    const float* w_src[7];
    const float* b_src[7];
    for (int i = 0; i < 7; i++) {
        w_src[i] = (const float*)d_in[1 + 2 * i];  // attk, attv, attr, atto, ffnk, ffnv, ffnr
        b_src[i] = (const float*)d_in[2 + 2 * i];
    }
    const float* ln1g = (const float*)d_in[15];
    const float* ln1b = (const float*)d_in[16];
    const float* ln2g = (const float*)d_in[17];
    const float* ln2b = (const float*)d_in[18];
    const float* mixk = (const float*)d_in[19];
    const float* mixv = (const float*)d_in[20];
    const float* mixr = (const float*)d_in[21];
    const float* fmk  = (const float*)d_in[22];
    const float* fmr  = (const float*)d_in[23];
    const float* tf   = (const float*)d_in[24];
    const float* td   = (const float*)d_in[25];
    float* out = (float*)d_out;

    float *p_xy, *p_mix, *p_k, *p_v, *p_r, *p_t0, *p_rz, *p_w;
    cudaGetSymbolAddress((void**)&p_xy,  g_xy);
    cudaGetSymbolAddress((void**)&p_mix, g_mix);
    cudaGetSymbolAddress((void**)&p_k,   g_k);
    cudaGetSymbolAddress((void**)&p_v,   g_v);
    cudaGetSymbolAddress((void**)&p_r,   g_r);
    cudaGetSymbolAddress((void**)&p_t0,  g_t0);
    cudaGetSymbolAddress((void**)&p_rz,  g_rz);
    cudaGetSymbolAddress((void**)&p_w,   g_w);

    const int n4w = DD * DD / 4;
    for (int i = 0; i < 7; i++)
        round_kernel<<<(n4w + 255) / 256, 256>>>((const float4*)w_src[i],
                                                 (float4*)(p_w + (size_t)i * DD * DD), n4w);

    const int nmix = TT * DD / 4 / 256;
    dim3 gg(TT / BM, DD / BN);
    dim3 gwkv(DD / 256, NCH);

    // --- attention branch ---
    ln_kernel<<<TT, 256>>>(x, ln1g, ln1b, p_xy);

    mix_kernel<<<nmix, 256>>>((const float4*)p_xy, mixk, (float4*)p_mix);
    gemm_kernel<0><<<gg, 256>>>(p_mix, p_w + 0 * (size_t)DD * DD, b_src[0], nullptr, nullptr, p_k);

    mix_kernel<<<nmix, 256>>>((const float4*)p_xy, mixv, (float4*)p_mix);
    gemm_kernel<0><<<gg, 256>>>(p_mix, p_w + 1 * (size_t)DD * DD, b_src[1], nullptr, nullptr, p_v);

    mix_kernel<<<nmix, 256>>>((const float4*)p_xy, mixr, (float4*)p_mix);
    gemm_kernel<1><<<gg, 256>>>(p_mix, p_w + 2 * (size_t)DD * DD, b_src[2], nullptr, nullptr, p_r);

    wkv_phase1<<<gwkv, 256>>>(p_k, p_v, td);
    wkv_phase2<<<DD / 256, 256>>>(td);
    wkv_phase3<<<gwkv, 256>>>(p_k, p_v, p_r, tf, td, p_t0);

    gemm_kernel<3><<<gg, 256>>>(p_t0, p_w + 3 * (size_t)DD * DD, b_src[3], x, nullptr, p_rz);

    // --- FFN branch ---
    ln_kernel<<<TT, 256>>>(p_rz, ln2g, ln2b, p_xy);

    mix_kernel<<<nmix, 256>>>((const float4*)p_xy, fmr, (float4*)p_mix);
    gemm_kernel<1><<<gg, 256>>>(p_mix, p_w + 6 * (size_t)DD * DD, b_src[6], nullptr, nullptr, p_r);

    mix_kernel<<<nmix, 256>>>((const float4*)p_xy, fmk, (float4*)p_mix);
    gemm_kernel<2><<<gg, 256>>>(p_mix, p_w + 4 * (size_t)DD * DD, b_src[4], nullptr, nullptr, p_t0);

    gemm_kernel<4><<<gg, 256>>>(p_t0, p_w + 5 * (size_t)DD * DD, b_src[5], p_r, p_rz, out);
}

// round 3
// speedup vs baseline: 2.1105x; 2.1105x over previous
#include <cuda_runtime.h>
#include <cuda_fp16.h>
#include <cstdint>

#define TT 8192
#define DD 2048
#define NCH 128
#define CL (TT/NCH)   // 64

// GEMM tiling (fp16 mma.sync m16n8k16)
#define BM 128
#define BN 128
#define BKH 64                    // K halves per stage = 128B row
#define NKT (DD / BKH)            // 32
#define NS 3
#define STAGE_B 32768             // A 16KB + B 16KB
#define SMEM_DYN (NS * STAGE_B)   // 98304

// ---------------- scratch (device globals; no allocations) ----------------
__device__ __half  g_xyh[(size_t)TT*DD];
__device__ __half  g_h0[(size_t)TT*DD];
__device__ __half  g_h1[(size_t)TT*DD];
__device__ __half  g_h2[(size_t)TT*DD];
__device__ __half  g_t0h[(size_t)TT*DD];
__device__ __half  g_wh[(size_t)7*DD*DD];
__device__ float g_k[(size_t)TT*DD];
__device__ float g_v[(size_t)TT*DD];
__device__ float g_r[(size_t)TT*DD];
__device__ float g_rz[(size_t)TT*DD];
__device__ float g_sa[NCH*DD], g_sb[NCH*DD], g_sp[NCH*DD];
__device__ float g_pa[NCH*DD], g_pb[NCH*DD], g_pp[NCH*DD];

// ---------------- helpers ----------------
__device__ __forceinline__ uint32_t saddr(const void* p) {
    return (uint32_t)__cvta_generic_to_shared(p);
}
__device__ __forceinline__ void cp_async16(uint32_t s, const void* g) {
    asm volatile("cp.async.cg.shared.global [%0], [%1], 16;" :: "r"(s), "l"(g));
}
__device__ __forceinline__ void cp_commit() {
    asm volatile("cp.async.commit_group;");
}
template <int N> __device__ __forceinline__ void cp_wait() {
    asm volatile("cp.async.wait_group %0;" :: "n"(N));
}
__device__ __forceinline__ void ldsm_x4(uint32_t r[4], uint32_t addr) {
    asm volatile("ldmatrix.sync.aligned.m8n8.x4.shared.b16 {%0,%1,%2,%3}, [%4];"
        : "=r"(r[0]), "=r"(r[1]), "=r"(r[2]), "=r"(r[3]) : "r"(addr));
}
__device__ __forceinline__ void mma16(float d[4], const uint32_t a[4],
                                      uint32_t b0, uint32_t b1) {
    asm volatile(
        "mma.sync.aligned.m16n8k16.row.col.f32.f16.f16.f32 "
        "{%0,%1,%2,%3}, {%4,%5,%6,%7}, {%8,%9}, {%0,%1,%2,%3};"
        : "+f"(d[0]), "+f"(d[1]), "+f"(d[2]), "+f"(d[3])
        : "r"(a[0]), "r"(a[1]), "r"(a[2]), "r"(a[3]), "r"(b0), "r"(b1));
}
#define SWZ(x) ((x) ^ (((x) >> 3) & 0x70))

// ---------------- elementwise kernels ----------------
__global__ __launch_bounds__(256) void wconv_kernel(const float2* __restrict__ in,
                                                    __half2* __restrict__ out, int n2) {
    int i = blockIdx.x * 256 + threadIdx.x;
    if (i < n2) {
        float2 v = in[i];
        out[i] = __floats2half2_rn(v.x, v.y);
    }
}

__global__ __launch_bounds__(256) void ln_kernel(const float* __restrict__ x,
                                                 const float* __restrict__ gw,
                                                 const float* __restrict__ gb,
                                                 __half* __restrict__ out) {
    int t = blockIdx.x;
    const float4* row = reinterpret_cast<const float4*>(x + (size_t)t * DD);
    float4 va[2];
    float s = 0.f, s2 = 0.f;
#pragma unroll
    for (int i = 0; i < 2; i++) {
        float4 v = row[threadIdx.x + i * 256];
        va[i] = v;
        s  += v.x + v.y + v.z + v.w;
        s2 += v.x*v.x + v.y*v.y + v.z*v.z + v.w*v.w;
    }
#pragma unroll
    for (int o = 16; o; o >>= 1) {
        s  += __shfl_xor_sync(0xffffffffu, s,  o);
        s2 += __shfl_xor_sync(0xffffffffu, s2, o);
    }
    __shared__ float ws[8], ws2[8];
    int wid = threadIdx.x >> 5, lane = threadIdx.x & 31;
    if (!lane) { ws[wid] = s; ws2[wid] = s2; }
    __syncthreads();
    float S = 0.f, S2 = 0.f;
#pragma unroll
    for (int i = 0; i < 8; i++) { S += ws[i]; S2 += ws2[i]; }
    float m = S * (1.0f / DD);
    float var = S2 * (1.0f / DD) - m * m;
    float inv = rsqrtf(var + 1e-5f);
    const float4* g4 = reinterpret_cast<const float4*>(gw);
    const float4* b4 = reinterpret_cast<const float4*>(gb);
    __half2* o2 = reinterpret_cast<__half2*>(out + (size_t)t * DD);
#pragma unroll
    for (int i = 0; i < 2; i++) {
        int c = threadIdx.x + i * 256;
        float4 v = va[i], g = g4[c], b = b4[c];
        float ox = (v.x - m) * inv * g.x + b.x;
        float oy = (v.y - m) * inv * g.y + b.y;
        float oz = (v.z - m) * inv * g.z + b.z;
        float ow = (v.w - m) * inv * g.w + b.w;
        o2[c * 2]     = __floats2half2_rn(ox, oy);
        o2[c * 2 + 1] = __floats2half2_rn(oz, ow);
    }
}

// N-way token-shift lerp: o_j = half( lerp(xy[t-1], xy[t], m_j) )
template <int N>
__global__ __launch_bounds__(256) void mixn_kernel(
    const __half2* __restrict__ xy,
    const float2* __restrict__ m0, const float2* __restrict__ m1,
    const float2* __restrict__ m2,
    __half2* __restrict__ o0, __half2* __restrict__ o1, __half2* __restrict__ o2) {
    int idx = blockIdx.x * 256 + threadIdx.x;
    const int DC = DD / 2;
    int t = idx / DC;
    int c = idx - t * DC;
    int tp = (t == 0) ? (TT - 1) : (t - 1);
    float2 a = __half22float2(xy[(size_t)tp * DC + c]);
    float2 b = __half22float2(xy[idx]);
    float2 mm;
    mm = m0[c];
    o0[idx] = __floats2half2_rn(a.x + mm.x * (b.x - a.x), a.y + mm.y * (b.y - a.y));
    mm = m1[c];
    o1[idx] = __floats2half2_rn(a.x + mm.x * (b.x - a.x), a.y + mm.y * (b.y - a.y));
    if (N == 3) {
        mm = m2[c];
        o2[idx] = __floats2half2_rn(a.x + mm.x * (b.x - a.x), a.y + mm.y * (b.y - a.y));
    }
}

// ---------------- WKV chunked scan ----------------
__global__ __launch_bounds__(256) void wkv_phase1(const float* __restrict__ k,
                                                  const float* __restrict__ v,
                                                  const float* __restrict__ td) {
    int c = blockIdx.x * 256 + threadIdx.x;
    int ch = blockIdx.y;
    float w = -__expf(td[c]);
    float aa = 0.f, bb = 0.f, pp = -1e38f;
    size_t base = (size_t)ch * CL * DD + c;
    for (int i = 0; i < CL; i++) {
        float kt = k[base + (size_t)i * DD];
        float vt = v[base + (size_t)i * DD];
        float ww2 = pp + w;
        float p2 = fmaxf(ww2, kt);
        float e1 = __expf(ww2 - p2), e2 = __expf(kt - p2);
        aa = e1 * aa + e2 * vt;
        bb = e1 * bb + e2;
        pp = p2;
    }
    int idx = ch * DD + c;
    g_sa[idx] = aa; g_sb[idx] = bb; g_sp[idx] = pp;
}

__global__ __launch_bounds__(256) void wkv_phase2(const float* __restrict__ td) {
    int c = blockIdx.x * 256 + threadIdx.x;
    float w = -__expf(td[c]);
    float clw = (float)CL * w;
    float aa = 0.f, bb = 0.f, pp = -1e38f;
    for (int ch = 0; ch < NCH; ch++) {
        int idx = ch * DD + c;
        g_pa[idx] = aa; g_pb[idx] = bb; g_pp[idx] = pp;
        float pd = pp + clw;
        float la = g_sa[idx], lb = g_sb[idx], lp = g_sp[idx];
        float p = fmaxf(pd, lp);
        float e1 = __expf(pd - p), e2 = __expf(lp - p);
        aa = e1 * aa + e2 * la;
        bb = e1 * bb + e2 * lb;
        pp = p;
    }
}

__global__ __launch_bounds__(256) void wkv_phase3(const float* __restrict__ k,
                                                  const float* __restrict__ v,
                                                  const float* __restrict__ r,
                                                  const float* __restrict__ tf,
                                                  const float* __restrict__ td,
                                                  __half* __restrict__ out) {
    int c = blockIdx.x * 256 + threadIdx.x;
    int ch = blockIdx.y;
    float w = -__expf(td[c]);
    float u = tf[c];
    int idx = ch * DD + c;
    float aa = g_pa[idx], bb = g_pb[idx], pp = g_pp[idx];
    size_t base = (size_t)ch * CL * DD + c;
    for (int i = 0; i < CL; i++) {
        size_t off = base + (size_t)i * DD;
        float kt = k[off], vt = v[off];
        float ww = u + kt;
        float p = fmaxf(pp, ww);
        float e1 = __expf(pp - p), e2 = __expf(ww - p);
        float o = (e1 * aa + e2 * vt) / (e1 * bb + e2);
        out[off] = __float2half_rn(o * r[off]);
        float ww2 = pp + w;
        float p2 = fmaxf(ww2, kt);
        e1 = __expf(ww2 - p2); e2 = __expf(kt - p2);
        aa = e1 * aa + e2 * vt;
        bb = e1 * bb + e2;
        pp = p2;
    }
}

// ---------------- fp16 mma.sync GEMM: out = epi(A @ W^T + bias) ----------------
// MODE 0: plain  1: sigmoid  2: relu^2 (->half)  3: +aux1  4: *aux1 + aux2
template <int MODE, typename OT>
__global__ __launch_bounds__(256, 2) void gemm_h(
    const __half* __restrict__ A, const __half* __restrict__ W,
    const float* __restrict__ bias,
    const float* __restrict__ aux1, const float* __restrict__ aux2,
    OT* __restrict__ out) {
    extern __shared__ __align__(1024) char smem[];
    const uint32_t sb = saddr(smem);
    const int tid = threadIdx.x;
    const int warp = tid >> 5, lane = tid & 31;
    const int bm = blockIdx.x * BM;
    const int bn = blockIdx.y * BN;
    const int wm = (warp >> 2) * 64;   // 2 warps over M
    const int wn = (warp & 3) * 32;    // 4 warps over N

    const __half* gA = A + (size_t)bm * DD;
    const __half* gB = W + (size_t)bn * DD;

    float acc[4][4][4];
#pragma unroll
    for (int i = 0; i < 4; i++)
#pragma unroll
        for (int j = 0; j < 4; j++)
#pragma unroll
            for (int q = 0; q < 4; q++) acc[i][j][q] = 0.f;

    auto load_stage = [&](int kt) {
        const uint32_t st = sb + (kt % NS) * STAGE_B;
        const int kk = kt * BKH;
#pragma unroll
        for (int i = 0; i < 4; i++) {
            const int idx = i * 256 + tid;
            const int row = idx >> 3;
            const int c16 = idx & 7;
            const uint32_t d = SWZ(row * 128 + c16 * 16);
            const size_t srcoff = (size_t)row * DD + kk + c16 * 8;
            cp_async16(st + d,         gA + srcoff);
            cp_async16(st + 16384 + d, gB + srcoff);
        }
    };

    load_stage(0); cp_commit();
    load_stage(1); cp_commit();

    // per-lane ldmatrix addressing pieces
    const int lrow = lane & 15;                   // row within 16-row tile pair
    const uint32_t kxor = (uint32_t)((lane & 7) << 4);
    const uint32_t khi  = (uint32_t)((lane >> 4) * 16);
    uint32_t arow_off[4], brow_off[2];
#pragma unroll
    for (int mi = 0; mi < 4; mi++) arow_off[mi] = (uint32_t)((wm + mi * 16 + lrow) * 128);
#pragma unroll
    for (int g = 0; g < 2; g++) brow_off[g] = (uint32_t)(16384 + (wn + g * 16 + lrow) * 128);

    for (int kt = 0; kt < NKT; kt++) {
        if (kt + 2 < NKT) load_stage(kt + 2);
        cp_commit();
        cp_wait<2>();
        __syncthreads();

        const uint32_t st = sb + (kt % NS) * STAGE_B;
#pragma unroll
        for (int ks = 0; ks < 4; ks++) {
            const uint32_t kpart = ((uint32_t)(ks * 32) + khi) ^ kxor;
            uint32_t af[4][4], bf[2][4];
#pragma unroll
            for (int mi = 0; mi < 4; mi++) ldsm_x4(af[mi], st + arow_off[mi] + kpart);
#pragma unroll
            for (int g = 0; g < 2; g++)   ldsm_x4(bf[g],  st + brow_off[g] + kpart);
#pragma unroll
            for (int mi = 0; mi < 4; mi++) {
                mma16(acc[mi][0], af[mi], bf[0][0], bf[0][2]);
                mma16(acc[mi][1], af[mi], bf[0][1], bf[0][3]);
                mma16(acc[mi][2], af[mi], bf[1][0], bf[1][2]);
                mma16(acc[mi][3], af[mi], bf[1][1], bf[1][3]);
            }
        }
        __syncthreads();
    }

    // ---------------- epilogue ----------------
    constexpr bool HALF_OUT = (sizeof(OT) == 2);
#pragma unroll
    for (int mi = 0; mi < 4; mi++) {
        const int r0 = bm + wm + mi * 16 + (lane >> 2);
#pragma unroll
        for (int ni = 0; ni < 4; ni++) {
            const int c0 = bn + wn + ni * 8 + (lane & 3) * 2;
            const float b0 = bias[c0], b1 = bias[c0 + 1];
            const size_t i0 = (size_t)r0 * DD + c0;
            const size_t i1 = (size_t)(r0 + 8) * DD + c0;
            float v[4];
            v[0] = acc[mi][ni][0] + b0;
            v[1] = acc[mi][ni][1] + b1;
            v[2] = acc[mi][ni][2] + b0;
            v[3] = acc[mi][ni][3] + b1;
            if (MODE == 1) {
#pragma unroll
                for (int q = 0; q < 4; q++) v[q] = 1.0f / (1.0f + expf(-v[q]));
            } else if (MODE == 2) {
#pragma unroll
                for (int q = 0; q < 4; q++) { float t = v[q] > 0.f ? v[q] : 0.f; v[q] = t * t; }
            } else if (MODE == 3) {
                v[0] += aux1[i0]; v[1] += aux1[i0 + 1];
                v[2] += aux1[i1]; v[3] += aux1[i1 + 1];
            } else if (MODE == 4) {
                v[0] = v[0] * aux1[i0]     + aux2[i0];
                v[1] = v[1] * aux1[i0 + 1] + aux2[i0 + 1];
                v[2] = v[2] * aux1[i1]     + aux2[i1];
                v[3] = v[3] * aux1[i1 + 1] + aux2[i1 + 1];
            }
            if (HALF_OUT) {
                __half2* o = reinterpret_cast<__half2*>((__half*)out + i0);
                *o = __floats2half2_rn(v[0], v[1]);
                __half2* o1p = reinterpret_cast<__half2*>((__half*)out + i1);
                *o1p = __floats2half2_rn(v[2], v[3]);
            } else {
                float* o = (float*)out;
                o[i0] = v[0]; o[i0 + 1] = v[1];
                o[i1] = v[2]; o[i1 + 1] = v[3];
            }
        }
    }
}

// ---------------- host orchestration ----------------
extern "C" void kernel_launch(void* const* d_in, const int* in_sizes, int n_in,
                              void* d_out, int out_size) {
    const float* x = (const float*)d_in[0];
    const float* w_src[7];
    const float* b_src[7];
    for (int i = 0; i < 7; i++) {
        w_src[i] = (const float*)d_in[1 + 2 * i];  // attk, attv, attr, atto, ffnk, ffnv, ffnr
        b_src[i] = (const float*)d_in[2 + 2 * i];
    }
    const float* ln1g = (const float*)d_in[15];
    const float* ln1b = (const float*)d_in[16];
    const float* ln2g = (const float*)d_in[17];
    const float* ln2b = (const float*)d_in[18];
    const float* mixk = (const float*)d_in[19];
    const float* mixv = (const float*)d_in[20];
    const float* mixr = (const float*)d_in[21];
    const float* fmk  = (const float*)d_in[22];
    const float* fmr  = (const float*)d_in[23];
    const float* tf   = (const float*)d_in[24];
    const float* td   = (const float*)d_in[25];
    float* out = (float*)d_out;

    __half *p_xyh, *p_h0, *p_h1, *p_h2, *p_t0h, *p_wh;
    float *p_k, *p_v, *p_r, *p_rz;
    cudaGetSymbolAddress((void**)&p_xyh, g_xyh);
    cudaGetSymbolAddress((void**)&p_h0,  g_h0);
    cudaGetSymbolAddress((void**)&p_h1,  g_h1);
    cudaGetSymbolAddress((void**)&p_h2,  g_h2);
    cudaGetSymbolAddress((void**)&p_t0h, g_t0h);
    cudaGetSymbolAddress((void**)&p_wh,  g_wh);
    cudaGetSymbolAddress((void**)&p_k,   g_k);
    cudaGetSymbolAddress((void**)&p_v,   g_v);
    cudaGetSymbolAddress((void**)&p_r,   g_r);
    cudaGetSymbolAddress((void**)&p_rz,  g_rz);

    cudaFuncSetAttribute(gemm_h<0, float>,  cudaFuncAttributeMaxDynamicSharedMemorySize, SMEM_DYN);
    cudaFuncSetAttribute(gemm_h<1, float>,  cudaFuncAttributeMaxDynamicSharedMemorySize, SMEM_DYN);
    cudaFuncSetAttribute(gemm_h<2, __half>, cudaFuncAttributeMaxDynamicSharedMemorySize, SMEM_DYN);
    cudaFuncSetAttribute(gemm_h<3, float>,  cudaFuncAttributeMaxDynamicSharedMemorySize, SMEM_DYN);
    cudaFuncSetAttribute(gemm_h<4, float>,  cudaFuncAttributeMaxDynamicSharedMemorySize, SMEM_DYN);

    const int n2w = DD * DD / 2;
    for (int i = 0; i < 7; i++)
        wconv_kernel<<<(n2w + 255) / 256, 256>>>((const float2*)w_src[i],
                                                 (__half2*)(p_wh + (size_t)i * DD * DD), n2w);

    const int nmix = TT * DD / 2 / 256;
    dim3 gg(TT / BM, DD / BN);   // (64, 16)
    dim3 gwkv(DD / 256, NCH);

    // --- attention branch ---
    ln_kernel<<<TT, 256>>>(x, ln1g, ln1b, p_xyh);
    mixn_kernel<3><<<nmix, 256>>>((const __half2*)p_xyh,
                                  (const float2*)mixk, (const float2*)mixv, (const float2*)mixr,
                                  (__half2*)p_h0, (__half2*)p_h1, (__half2*)p_h2);

    gemm_h<0, float><<<gg, 256, SMEM_DYN>>>(p_h0, p_wh + 0 * (size_t)DD * DD, b_src[0], nullptr, nullptr, p_k);
    gemm_h<0, float><<<gg, 256, SMEM_DYN>>>(p_h1, p_wh + 1 * (size_t)DD * DD, b_src[1], nullptr, nullptr, p_v);
    gemm_h<1, float><<<gg, 256, SMEM_DYN>>>(p_h2, p_wh + 2 * (size_t)DD * DD, b_src[2], nullptr, nullptr, p_r);

    wkv_phase1<<<gwkv, 256>>>(p_k, p_v, td);
    wkv_phase2<<<DD / 256, 256>>>(td);
    wkv_phase3<<<gwkv, 256>>>(p_k, p_v, p_r, tf, td, p_t0h);

    gemm_h<3, float><<<gg, 256, SMEM_DYN>>>(p_t0h, p_wh + 3 * (size_t)DD * DD, b_src[3], x, nullptr, p_rz);

    // --- FFN branch ---
    ln_kernel<<<TT, 256>>>(p_rz, ln2g, ln2b, p_xyh);
    mixn_kernel<2><<<nmix, 256>>>((const __half2*)p_xyh,
                                  (const float2*)fmr, (const float2*)fmk, nullptr,
                                  (__half2*)p_h0, (__half2*)p_h1, nullptr);

    gemm_h<1, float><<<gg, 256, SMEM_DYN>>>(p_h0, p_wh + 6 * (size_t)DD * DD, b_src[6], nullptr, nullptr, p_r);
    gemm_h<2, __half><<<gg, 256, SMEM_DYN>>>(p_h1, p_wh + 4 * (size_t)DD * DD, b_src[4], nullptr, nullptr, p_t0h);
    gemm_h<4, float><<<gg, 256, SMEM_DYN>>>(p_t0h, p_wh + 5 * (size_t)DD * DD, b_src[5], p_r, p_rz, out);
}

// round 4
// speedup vs baseline: 2.1841x; 1.0349x over previous
#include <cuda_runtime.h>
#include <cuda_fp16.h>
#include <cstdint>

#define TT 8192
#define DD 2048
#define NCH 128
#define CL (TT/NCH)   // 64

// GEMM tiling (fp16 mma.sync m16n8k16), 4 warps, warp tile 64x64
#define BM 128
#define BN 128
#define BKH 64                    // K halves per stage = 128B row
#define NKT (DD / BKH)            // 32
#define NS 3
#define STAGE_B 32768             // A 16KB + B 16KB
#define SMEM_DYN (NS * STAGE_B)   // 98304

// ---------------- scratch (device globals; no allocations) ----------------
__device__ __half  g_xyh[(size_t)TT*DD];
__device__ __half  g_h0[(size_t)TT*DD];
__device__ __half  g_h1[(size_t)TT*DD];
__device__ __half  g_h2[(size_t)TT*DD];
__device__ __half  g_t0h[(size_t)TT*DD];
__device__ __half  g_wh[(size_t)7*DD*DD];
__device__ float g_k[(size_t)TT*DD];
__device__ float g_v[(size_t)TT*DD];
__device__ float g_r[(size_t)TT*DD];
__device__ float g_rz[(size_t)TT*DD];
__device__ float g_sa[NCH*DD], g_sb[NCH*DD], g_sp[NCH*DD];
__device__ float g_pa[NCH*DD], g_pb[NCH*DD], g_pp[NCH*DD];

// ---------------- helpers ----------------
__device__ __forceinline__ uint32_t saddr(const void* p) {
    return (uint32_t)__cvta_generic_to_shared(p);
}
__device__ __forceinline__ void cp_async16(uint32_t s, const void* g) {
    asm volatile("cp.async.cg.shared.global [%0], [%1], 16;" :: "r"(s), "l"(g));
}
__device__ __forceinline__ void cp_commit() {
    asm volatile("cp.async.commit_group;");
}
template <int N> __device__ __forceinline__ void cp_wait() {
    asm volatile("cp.async.wait_group %0;" :: "n"(N));
}
__device__ __forceinline__ void ldsm_x4(uint32_t r[4], uint32_t addr) {
    asm volatile("ldmatrix.sync.aligned.m8n8.x4.shared.b16 {%0,%1,%2,%3}, [%4];"
        : "=r"(r[0]), "=r"(r[1]), "=r"(r[2]), "=r"(r[3]) : "r"(addr));
}
__device__ __forceinline__ void mma16(float d[4], const uint32_t a[4],
                                      uint32_t b0, uint32_t b1) {
    asm volatile(
        "mma.sync.aligned.m16n8k16.row.col.f32.f16.f16.f32 "
        "{%0,%1,%2,%3}, {%4,%5,%6,%7}, {%8,%9}, {%0,%1,%2,%3};"
        : "+f"(d[0]), "+f"(d[1]), "+f"(d[2]), "+f"(d[3])
        : "r"(a[0]), "r"(a[1]), "r"(a[2]), "r"(a[3]), "r"(b0), "r"(b1));
}
#define SWZ(x) ((x) ^ (((x) >> 3) & 0x70))

// ---------------- elementwise kernels ----------------
// all 7 weights fp32 -> fp16 in one launch
__global__ __launch_bounds__(256) void wconv7_kernel(
    const float4* __restrict__ w0, const float4* __restrict__ w1,
    const float4* __restrict__ w2, const float4* __restrict__ w3,
    const float4* __restrict__ w4, const float4* __restrict__ w5,
    const float4* __restrict__ w6, __half2* __restrict__ out) {
    const int per = DD * DD / 4;
    int i = blockIdx.x * 256 + threadIdx.x;
    int w = i / per;
    int j = i - w * per;
    const float4* src;
    switch (w) {
        case 0: src = w0; break; case 1: src = w1; break;
        case 2: src = w2; break; case 3: src = w3; break;
        case 4: src = w4; break; case 5: src = w5; break;
        default: src = w6; break;
    }
    float4 v = src[j];
    __half2* o = out + (size_t)w * (DD * DD / 2) + (size_t)j * 2;
    o[0] = __floats2half2_rn(v.x, v.y);
    o[1] = __floats2half2_rn(v.z, v.w);
}

__global__ __launch_bounds__(256) void ln_kernel(const float* __restrict__ x,
                                                 const float* __restrict__ gw,
                                                 const float* __restrict__ gb,
                                                 __half* __restrict__ out) {
    int t = blockIdx.x;
    const float4* row = reinterpret_cast<const float4*>(x + (size_t)t * DD);
    float4 va[2];
    float s = 0.f, s2 = 0.f;
#pragma unroll
    for (int i = 0; i < 2; i++) {
        float4 v = row[threadIdx.x + i * 256];
        va[i] = v;
        s  += v.x + v.y + v.z + v.w;
        s2 += v.x*v.x + v.y*v.y + v.z*v.z + v.w*v.w;
    }
#pragma unroll
    for (int o = 16; o; o >>= 1) {
        s  += __shfl_xor_sync(0xffffffffu, s,  o);
        s2 += __shfl_xor_sync(0xffffffffu, s2, o);
    }
    __shared__ float ws[8], ws2[8];
    int wid = threadIdx.x >> 5, lane = threadIdx.x & 31;
    if (!lane) { ws[wid] = s; ws2[wid] = s2; }
    __syncthreads();
    float S = 0.f, S2 = 0.f;
#pragma unroll
    for (int i = 0; i < 8; i++) { S += ws[i]; S2 += ws2[i]; }
    float m = S * (1.0f / DD);
    float var = S2 * (1.0f / DD) - m * m;
    float inv = rsqrtf(var + 1e-5f);
    const float4* g4 = reinterpret_cast<const float4*>(gw);
    const float4* b4 = reinterpret_cast<const float4*>(gb);
    __half2* o2 = reinterpret_cast<__half2*>(out + (size_t)t * DD);
#pragma unroll
    for (int i = 0; i < 2; i++) {
        int c = threadIdx.x + i * 256;
        float4 v = va[i], g = g4[c], b = b4[c];
        float ox = (v.x - m) * inv * g.x + b.x;
        float oy = (v.y - m) * inv * g.y + b.y;
        float oz = (v.z - m) * inv * g.z + b.z;
        float ow = (v.w - m) * inv * g.w + b.w;
        o2[c * 2]     = __floats2half2_rn(ox, oy);
        o2[c * 2 + 1] = __floats2half2_rn(oz, ow);
    }
}

// N-way token-shift lerp
template <int N>
__global__ __launch_bounds__(256) void mixn_kernel(
    const __half2* __restrict__ xy,
    const float2* __restrict__ m0, const float2* __restrict__ m1,
    const float2* __restrict__ m2,
    __half2* __restrict__ o0, __half2* __restrict__ o1, __half2* __restrict__ o2) {
    int idx = blockIdx.x * 256 + threadIdx.x;
    const int DC = DD / 2;
    int t = idx / DC;
    int c = idx - t * DC;
    int tp = (t == 0) ? (TT - 1) : (t - 1);
    float2 a = __half22float2(xy[(size_t)tp * DC + c]);
    float2 b = __half22float2(xy[idx]);
    float2 mm;
    mm = m0[c];
    o0[idx] = __floats2half2_rn(a.x + mm.x * (b.x - a.x), a.y + mm.y * (b.y - a.y));
    mm = m1[c];
    o1[idx] = __floats2half2_rn(a.x + mm.x * (b.x - a.x), a.y + mm.y * (b.y - a.y));
    if (N == 3) {
        mm = m2[c];
        o2[idx] = __floats2half2_rn(a.x + mm.x * (b.x - a.x), a.y + mm.y * (b.y - a.y));
    }
}

// ---------------- WKV chunked scan ----------------
__global__ __launch_bounds__(256) void wkv_phase1(const float* __restrict__ k,
                                                  const float* __restrict__ v,
                                                  const float* __restrict__ td) {
    int c = blockIdx.x * 256 + threadIdx.x;
    int ch = blockIdx.y;
    float w = -__expf(td[c]);
    float aa = 0.f, bb = 0.f, pp = -1e38f;
    size_t base = (size_t)ch * CL * DD + c;
    for (int i = 0; i < CL; i++) {
        float kt = k[base + (size_t)i * DD];
        float vt = v[base + (size_t)i * DD];
        float ww2 = pp + w;
        float p2 = fmaxf(ww2, kt);
        float e1 = __expf(ww2 - p2), e2 = __expf(kt - p2);
        aa = e1 * aa + e2 * vt;
        bb = e1 * bb + e2;
        pp = p2;
    }
    int idx = ch * DD + c;
    g_sa[idx] = aa; g_sb[idx] = bb; g_sp[idx] = pp;
}

__global__ __launch_bounds__(256) void wkv_phase2(const float* __restrict__ td) {
    int c = blockIdx.x * 256 + threadIdx.x;
    float w = -__expf(td[c]);
    float clw = (float)CL * w;
    float aa = 0.f, bb = 0.f, pp = -1e38f;
    for (int ch = 0; ch < NCH; ch++) {
        int idx = ch * DD + c;
        g_pa[idx] = aa; g_pb[idx] = bb; g_pp[idx] = pp;
        float pd = pp + clw;
        float la = g_sa[idx], lb = g_sb[idx], lp = g_sp[idx];
        float p = fmaxf(pd, lp);
        float e1 = __expf(pd - p), e2 = __expf(lp - p);
        aa = e1 * aa + e2 * la;
        bb = e1 * bb + e2 * lb;
        pp = p;
    }
}

__global__ __launch_bounds__(256) void wkv_phase3(const float* __restrict__ k,
                                                  const float* __restrict__ v,
                                                  const float* __restrict__ r,
                                                  const float* __restrict__ tf,
                                                  const float* __restrict__ td,
                                                  __half* __restrict__ out) {
    int c = blockIdx.x * 256 + threadIdx.x;
    int ch = blockIdx.y;
    float w = -__expf(td[c]);
    float u = tf[c];
    int idx = ch * DD + c;
    float aa = g_pa[idx], bb = g_pb[idx], pp = g_pp[idx];
    size_t base = (size_t)ch * CL * DD + c;
    for (int i = 0; i < CL; i++) {
        size_t off = base + (size_t)i * DD;
        float kt = k[off], vt = v[off];
        float ww = u + kt;
        float p = fmaxf(pp, ww);
        float e1 = __expf(pp - p), e2 = __expf(ww - p);
        float o = (e1 * aa + e2 * vt) / (e1 * bb + e2);
        out[off] = __float2half_rn(o * r[off]);
        float ww2 = pp + w;
        float p2 = fmaxf(ww2, kt);
        e1 = __expf(ww2 - p2); e2 = __expf(kt - p2);
        aa = e1 * aa + e2 * vt;
        bb = e1 * bb + e2;
        pp = p2;
    }
}

// ---------------- fp16 mma.sync GEMM, 4 warps, 64x64 warp tiles ----------------
// MODE 0: plain  1: sigmoid  2: relu^2 (->half)  3: +aux1  4: *aux1 + aux2
template <int MODE, typename OT>
__global__ __launch_bounds__(128, 2) void gemm_h(
    const __half* __restrict__ A, const __half* __restrict__ W,
    const float* __restrict__ bias,
    const float* __restrict__ aux1, const float* __restrict__ aux2,
    OT* __restrict__ out) {
    extern __shared__ __align__(1024) char smem[];
    const uint32_t sb = saddr(smem);
    const int tid = threadIdx.x;
    const int warp = tid >> 5, lane = tid & 31;
    const int bm = blockIdx.x * BM;
    const int bn = blockIdx.y * BN;
    const int wm = (warp >> 1) * 64;   // 2 warps over M
    const int wn = (warp & 1) * 64;    // 2 warps over N

    const __half* gA = A + (size_t)bm * DD;
    const __half* gB = W + (size_t)bn * DD;

    float acc[4][8][4];
#pragma unroll
    for (int i = 0; i < 4; i++)
#pragma unroll
        for (int j = 0; j < 8; j++)
#pragma unroll
            for (int q = 0; q < 4; q++) acc[i][j][q] = 0.f;

    auto load_stage = [&](int kt) {
        const uint32_t st = sb + (kt % NS) * STAGE_B;
        const int kk = kt * BKH;
#pragma unroll
        for (int i = 0; i < 8; i++) {
            const int idx = i * 128 + tid;
            const int row = idx >> 3;
            const int c16 = idx & 7;
            const uint32_t d = SWZ(row * 128 + c16 * 16);
            const size_t srcoff = (size_t)row * DD + kk + c16 * 8;
            cp_async16(st + d,         gA + srcoff);
            cp_async16(st + 16384 + d, gB + srcoff);
        }
    };

    load_stage(0); cp_commit();
    load_stage(1); cp_commit();

    // per-lane ldmatrix addressing
    const int lrow = lane & 15;
    const uint32_t kxor = (uint32_t)((lane & 7) << 4);
    const uint32_t khi  = (uint32_t)((lane >> 4) * 16);
    uint32_t arow_off[4], brow_off[4];
#pragma unroll
    for (int mi = 0; mi < 4; mi++) arow_off[mi] = (uint32_t)((wm + mi * 16 + lrow) * 128);
#pragma unroll
    for (int g = 0; g < 4; g++) brow_off[g] = (uint32_t)(16384 + (wn + g * 16 + lrow) * 128);

    uint32_t af[2][4][4], bf[2][4][4];

    auto load_frags = [&](const uint32_t st, int ks, int buf) {
        const uint32_t kpart = ((uint32_t)(ks * 32) + khi) ^ kxor;
#pragma unroll
        for (int mi = 0; mi < 4; mi++) ldsm_x4(af[buf][mi], st + arow_off[mi] + kpart);
#pragma unroll
        for (int g = 0; g < 4; g++)   ldsm_x4(bf[buf][g],  st + brow_off[g] + kpart);
    };

    for (int kt = 0; kt < NKT; kt++) {
        if (kt + 2 < NKT) load_stage(kt + 2);
        cp_commit();
        cp_wait<2>();
        __syncthreads();

        const uint32_t st = sb + (kt % NS) * STAGE_B;
        load_frags(st, 0, 0);
#pragma unroll
        for (int ks = 0; ks < 4; ks++) {
            const int cur = ks & 1;
            if (ks < 3) load_frags(st, ks + 1, cur ^ 1);
#pragma unroll
            for (int mi = 0; mi < 4; mi++)
#pragma unroll
                for (int g = 0; g < 4; g++) {
                    mma16(acc[mi][2 * g],     af[cur][mi], bf[cur][g][0], bf[cur][g][2]);
                    mma16(acc[mi][2 * g + 1], af[cur][mi], bf[cur][g][1], bf[cur][g][3]);
                }
        }
        __syncthreads();
    }

    // ---------------- epilogue ----------------
    constexpr bool HALF_OUT = (sizeof(OT) == 2);
#pragma unroll
    for (int mi = 0; mi < 4; mi++) {
        const int r0 = bm + wm + mi * 16 + (lane >> 2);
#pragma unroll
        for (int ni = 0; ni < 8; ni++) {
            const int c0 = bn + wn + ni * 8 + (lane & 3) * 2;
            const float b0 = bias[c0], b1 = bias[c0 + 1];
            const size_t i0 = (size_t)r0 * DD + c0;
            const size_t i1 = (size_t)(r0 + 8) * DD + c0;
            float v[4];
            v[0] = acc[mi][ni][0] + b0;
            v[1] = acc[mi][ni][1] + b1;
            v[2] = acc[mi][ni][2] + b0;
            v[3] = acc[mi][ni][3] + b1;
            if (MODE == 1) {
#pragma unroll
                for (int q = 0; q < 4; q++) v[q] = 1.0f / (1.0f + expf(-v[q]));
            } else if (MODE == 2) {
#pragma unroll
                for (int q = 0; q < 4; q++) { float t = v[q] > 0.f ? v[q] : 0.f; v[q] = t * t; }
            } else if (MODE == 3) {
                v[0] += aux1[i0]; v[1] += aux1[i0 + 1];
                v[2] += aux1[i1]; v[3] += aux1[i1 + 1];
            } else if (MODE == 4) {
                v[0] = v[0] * aux1[i0]     + aux2[i0];
                v[1] = v[1] * aux1[i0 + 1] + aux2[i0 + 1];
                v[2] = v[2] * aux1[i1]     + aux2[i1];
                v[3] = v[3] * aux1[i1 + 1] + aux2[i1 + 1];
            }
            if (HALF_OUT) {
                *reinterpret_cast<__half2*>((__half*)out + i0) = __floats2half2_rn(v[0], v[1]);
                *reinterpret_cast<__half2*>((__half*)out + i1) = __floats2half2_rn(v[2], v[3]);
            } else {
                float* o = (float*)out;
                o[i0] = v[0]; o[i0 + 1] = v[1];
                o[i1] = v[2]; o[i1 + 1] = v[3];
            }
        }
    }
}

// ---------------- host orchestration ----------------
extern "C" void kernel_launch(void* const* d_in, const int* in_sizes, int n_in,
                              void* d_out, int out_size) {
    const float* x = (const float*)d_in[0];
    const float* w_src[7];
    const float* b_src[7];
    for (int i = 0; i < 7; i++) {
        w_src[i] = (const float*)d_in[1 + 2 * i];
        b_src[i] = (const float*)d_in[2 + 2 * i];
    }
    const float* ln1g = (const float*)d_in[15];
    const float* ln1b = (const float*)d_in[16];
    const float* ln2g = (const float*)d_in[17];
    const float* ln2b = (const float*)d_in[18];
    const float* mixk = (const float*)d_in[19];
    const float* mixv = (const float*)d_in[20];
    const float* mixr = (const float*)d_in[21];
    const float* fmk  = (const float*)d_in[22];
    const float* fmr  = (const float*)d_in[23];
    const float* tf   = (const float*)d_in[24];
    const float* td   = (const float*)d_in[25];
    float* out = (float*)d_out;

    __half *p_xyh, *p_h0, *p_h1, *p_h2, *p_t0h, *p_wh;
    float *p_k, *p_v, *p_r, *p_rz;
    cudaGetSymbolAddress((void**)&p_xyh, g_xyh);
    cudaGetSymbolAddress((void**)&p_h0,  g_h0);
    cudaGetSymbolAddress((void**)&p_h1,  g_h1);
    cudaGetSymbolAddress((void**)&p_h2,  g_h2);
    cudaGetSymbolAddress((void**)&p_t0h, g_t0h);
    cudaGetSymbolAddress((void**)&p_wh,  g_wh);
    cudaGetSymbolAddress((void**)&p_k,   g_k);
    cudaGetSymbolAddress((void**)&p_v,   g_v);
    cudaGetSymbolAddress((void**)&p_r,   g_r);
    cudaGetSymbolAddress((void**)&p_rz,  g_rz);

    cudaFuncSetAttribute(gemm_h<0, float>,  cudaFuncAttributeMaxDynamicSharedMemorySize, SMEM_DYN);
    cudaFuncSetAttribute(gemm_h<1, float>,  cudaFuncAttributeMaxDynamicSharedMemorySize, SMEM_DYN);
    cudaFuncSetAttribute(gemm_h<2, __half>, cudaFuncAttributeMaxDynamicSharedMemorySize, SMEM_DYN);
    cudaFuncSetAttribute(gemm_h<3, float>,  cudaFuncAttributeMaxDynamicSharedMemorySize, SMEM_DYN);
    cudaFuncSetAttribute(gemm_h<4, float>,  cudaFuncAttributeMaxDynamicSharedMemorySize, SMEM_DYN);

    const int nwc = 7 * (DD * DD / 4) / 256;
    wconv7_kernel<<<nwc, 256>>>((const float4*)w_src[0], (const float4*)w_src[1],
                                (const float4*)w_src[2], (const float4*)w_src[3],
                                (const float4*)w_src[4], (const float4*)w_src[5],
                                (const float4*)w_src[6], (__half2*)p_wh);

    const int nmix = TT * DD / 2 / 256;
    dim3 gg(TT / BM, DD / BN);   // (64, 16)
    dim3 gwkv(DD / 256, NCH);

    // --- attention branch ---
    ln_kernel<<<TT, 256>>>(x, ln1g, ln1b, p_xyh);
    mixn_kernel<3><<<nmix, 256>>>((const __half2*)p_xyh,
                                  (const float2*)mixk, (const float2*)mixv, (const float2*)mixr,
                                  (__half2*)p_h0, (__half2*)p_h1, (__half2*)p_h2);

    gemm_h<0, float><<<gg, 128, SMEM_DYN>>>(p_h0, p_wh + 0 * (size_t)DD * DD, b_src[0], nullptr, nullptr, p_k);
    gemm_h<0, float><<<gg, 128, SMEM_DYN>>>(p_h1, p_wh + 1 * (size_t)DD * DD, b_src[1], nullptr, nullptr, p_v);
    gemm_h<1, float><<<gg, 128, SMEM_DYN>>>(p_h2, p_wh + 2 * (size_t)DD * DD, b_src[2], nullptr, nullptr, p_r);

    wkv_phase1<<<gwkv, 256>>>(p_k, p_v, td);
    wkv_phase2<<<DD / 256, 256>>>(td);
    wkv_phase3<<<gwkv, 256>>>(p_k, p_v, p_r, tf, td, p_t0h);

    gemm_h<3, float><<<gg, 128, SMEM_DYN>>>(p_t0h, p_wh + 3 * (size_t)DD * DD, b_src[3], x, nullptr, p_rz);

    // --- FFN branch ---
    ln_kernel<<<TT, 256>>>(p_rz, ln2g, ln2b, p_xyh);
    mixn_kernel<2><<<nmix, 256>>>((const __half2*)p_xyh,
                                  (const float2*)fmr, (const float2*)fmk, nullptr,
                                  (__half2*)p_h0, (__half2*)p_h1, nullptr);

    gemm_h<1, float><<<gg, 128, SMEM_DYN>>>(p_h0, p_wh + 6 * (size_t)DD * DD, b_src[6], nullptr, nullptr, p_r);
    gemm_h<2, __half><<<gg, 128, SMEM_DYN>>>(p_h1, p_wh + 4 * (size_t)DD * DD, b_src[4], nullptr, nullptr, p_t0h);
    gemm_h<4, float><<<gg, 128, SMEM_DYN>>>(p_t0h, p_wh + 5 * (size_t)DD * DD, b_src[5], p_r, p_rz, out);
}

// round 5
// speedup vs baseline: 2.1927x; 1.0039x over previous
#include <cuda_runtime.h>
#include <cuda_fp16.h>
#include <cstdint>

#define TT 8192
#define DD 2048
#define NCH 128
#define CL (TT/NCH)   // 64

// GEMM tiling (fp16 mma.sync m16n8k16), 4 warps, warp tile 64x64
#define BM 128
#define BN 128
#define BKH 64                    // K halves per stage = 128B row
#define NKT (DD / BKH)            // 32
#define NS 3
#define STAGE_B 32768             // A 16KB + B 16KB
#define SMEM_DYN (NS * STAGE_B)   // 98304

// ---------------- scratch (device globals; no allocations) ----------------
__device__ __half  g_xyh[(size_t)TT*DD];
__device__ __half  g_h0[(size_t)TT*DD];
__device__ __half  g_h1[(size_t)TT*DD];
__device__ __half  g_h2[(size_t)TT*DD];
__device__ __half  g_t0h[(size_t)TT*DD];
__device__ __half  g_wh[(size_t)7*DD*DD];
__device__ float g_k[(size_t)TT*DD];
__device__ float g_v[(size_t)TT*DD];
__device__ float g_r[(size_t)TT*DD];
__device__ float g_rz[(size_t)TT*DD];
__device__ float g_sa[NCH*DD], g_sb[NCH*DD], g_sp[NCH*DD];
__device__ float g_pa[NCH*DD], g_pb[NCH*DD], g_pp[NCH*DD];

// ---------------- helpers ----------------
__device__ __forceinline__ uint32_t saddr(const void* p) {
    return (uint32_t)__cvta_generic_to_shared(p);
}
__device__ __forceinline__ void cp_async16(uint32_t s, const void* g) {
    asm volatile("cp.async.cg.shared.global [%0], [%1], 16;" :: "r"(s), "l"(g));
}
__device__ __forceinline__ void cp_commit() {
    asm volatile("cp.async.commit_group;");
}
template <int N> __device__ __forceinline__ void cp_wait() {
    asm volatile("cp.async.wait_group %0;" :: "n"(N));
}
__device__ __forceinline__ void ldsm_x4(uint32_t r[4], uint32_t addr) {
    asm volatile("ldmatrix.sync.aligned.m8n8.x4.shared.b16 {%0,%1,%2,%3}, [%4];"
        : "=r"(r[0]), "=r"(r[1]), "=r"(r[2]), "=r"(r[3]) : "r"(addr));
}
__device__ __forceinline__ void mma16(float d[4], const uint32_t a[4],
                                      uint32_t b0, uint32_t b1) {
    asm volatile(
        "mma.sync.aligned.m16n8k16.row.col.f32.f16.f16.f32 "
        "{%0,%1,%2,%3}, {%4,%5,%6,%7}, {%8,%9}, {%0,%1,%2,%3};"
        : "+f"(d[0]), "+f"(d[1]), "+f"(d[2]), "+f"(d[3])
        : "r"(a[0]), "r"(a[1]), "r"(a[2]), "r"(a[3]), "r"(b0), "r"(b1));
}
#define SWZ(x) ((x) ^ (((x) >> 3) & 0x70))

// ---------------- elementwise kernels ----------------
__global__ __launch_bounds__(256) void wconv7_kernel(
    const float4* __restrict__ w0, const float4* __restrict__ w1,
    const float4* __restrict__ w2, const float4* __restrict__ w3,
    const float4* __restrict__ w4, const float4* __restrict__ w5,
    const float4* __restrict__ w6, __half2* __restrict__ out) {
    const int per = DD * DD / 4;
    int i = blockIdx.x * 256 + threadIdx.x;
    int w = i / per;
    int j = i - w * per;
    const float4* src;
    switch (w) {
        case 0: src = w0; break; case 1: src = w1; break;
        case 2: src = w2; break; case 3: src = w3; break;
        case 4: src = w4; break; case 5: src = w5; break;
        default: src = w6; break;
    }
    float4 v = src[j];
    __half2* o = out + (size_t)w * (DD * DD / 2) + (size_t)j * 2;
    o[0] = __floats2half2_rn(v.x, v.y);
    o[1] = __floats2half2_rn(v.z, v.w);
}

__global__ __launch_bounds__(256) void ln_kernel(const float* __restrict__ x,
                                                 const float* __restrict__ gw,
                                                 const float* __restrict__ gb,
                                                 __half* __restrict__ out) {
    int t = blockIdx.x;
    const float4* row = reinterpret_cast<const float4*>(x + (size_t)t * DD);
    float4 va[2];
    float s = 0.f, s2 = 0.f;
#pragma unroll
    for (int i = 0; i < 2; i++) {
        float4 v = row[threadIdx.x + i * 256];
        va[i] = v;
        s  += v.x + v.y + v.z + v.w;
        s2 += v.x*v.x + v.y*v.y + v.z*v.z + v.w*v.w;
    }
#pragma unroll
    for (int o = 16; o; o >>= 1) {
        s  += __shfl_xor_sync(0xffffffffu, s,  o);
        s2 += __shfl_xor_sync(0xffffffffu, s2, o);
    }
    __shared__ float ws[8], ws2[8];
    int wid = threadIdx.x >> 5, lane = threadIdx.x & 31;
    if (!lane) { ws[wid] = s; ws2[wid] = s2; }
    __syncthreads();
    float S = 0.f, S2 = 0.f;
#pragma unroll
    for (int i = 0; i < 8; i++) { S += ws[i]; S2 += ws2[i]; }
    float m = S * (1.0f / DD);
    float var = S2 * (1.0f / DD) - m * m;
    float inv = rsqrtf(var + 1e-5f);
    const float4* g4 = reinterpret_cast<const float4*>(gw);
    const float4* b4 = reinterpret_cast<const float4*>(gb);
    __half2* o2 = reinterpret_cast<__half2*>(out + (size_t)t * DD);
#pragma unroll
    for (int i = 0; i < 2; i++) {
        int c = threadIdx.x + i * 256;
        float4 v = va[i], g = g4[c], b = b4[c];
        float ox = (v.x - m) * inv * g.x + b.x;
        float oy = (v.y - m) * inv * g.y + b.y;
        float oz = (v.z - m) * inv * g.z + b.z;
        float ow = (v.w - m) * inv * g.w + b.w;
        o2[c * 2]     = __floats2half2_rn(ox, oy);
        o2[c * 2 + 1] = __floats2half2_rn(oz, ow);
    }
}

template <int N>
__global__ __launch_bounds__(256) void mixn_kernel(
    const __half2* __restrict__ xy,
    const float2* __restrict__ m0, const float2* __restrict__ m1,
    const float2* __restrict__ m2,
    __half2* __restrict__ o0, __half2* __restrict__ o1, __half2* __restrict__ o2) {
    int idx = blockIdx.x * 256 + threadIdx.x;
    const int DC = DD / 2;
    int t = idx / DC;
    int c = idx - t * DC;
    int tp = (t == 0) ? (TT - 1) : (t - 1);
    float2 a = __half22float2(xy[(size_t)tp * DC + c]);
    float2 b = __half22float2(xy[idx]);
    float2 mm;
    mm = m0[c];
    o0[idx] = __floats2half2_rn(a.x + mm.x * (b.x - a.x), a.y + mm.y * (b.y - a.y));
    mm = m1[c];
    o1[idx] = __floats2half2_rn(a.x + mm.x * (b.x - a.x), a.y + mm.y * (b.y - a.y));
    if (N == 3) {
        mm = m2[c];
        o2[idx] = __floats2half2_rn(a.x + mm.x * (b.x - a.x), a.y + mm.y * (b.y - a.y));
    }
}

// ---------------- WKV chunked scan ----------------
__global__ __launch_bounds__(256) void wkv_phase1(const float* __restrict__ k,
                                                  const float* __restrict__ v,
                                                  const float* __restrict__ td) {
    int c = blockIdx.x * 256 + threadIdx.x;
    int ch = blockIdx.y;
    float w = -__expf(td[c]);
    float aa = 0.f, bb = 0.f, pp = -1e38f;
    size_t base = (size_t)ch * CL * DD + c;
    for (int i = 0; i < CL; i++) {
        float kt = k[base + (size_t)i * DD];
        float vt = v[base + (size_t)i * DD];
        float ww2 = pp + w;
        float p2 = fmaxf(ww2, kt);
        float e1 = __expf(ww2 - p2), e2 = __expf(kt - p2);
        aa = e1 * aa + e2 * vt;
        bb = e1 * bb + e2;
        pp = p2;
    }
    int idx = ch * DD + c;
    g_sa[idx] = aa; g_sb[idx] = bb; g_sp[idx] = pp;
}

__global__ __launch_bounds__(256) void wkv_phase2(const float* __restrict__ td) {
    int c = blockIdx.x * 256 + threadIdx.x;
    float w = -__expf(td[c]);
    float clw = (float)CL * w;
    float aa = 0.f, bb = 0.f, pp = -1e38f;
    for (int ch = 0; ch < NCH; ch++) {
        int idx = ch * DD + c;
        g_pa[idx] = aa; g_pb[idx] = bb; g_pp[idx] = pp;
        float pd = pp + clw;
        float la = g_sa[idx], lb = g_sb[idx], lp = g_sp[idx];
        float p = fmaxf(pd, lp);
        float e1 = __expf(pd - p), e2 = __expf(lp - p);
        aa = e1 * aa + e2 * la;
        bb = e1 * bb + e2 * lb;
        pp = p;
    }
}

__global__ __launch_bounds__(256) void wkv_phase3(const float* __restrict__ k,
                                                  const float* __restrict__ v,
                                                  const float* __restrict__ r,
                                                  const float* __restrict__ tf,
                                                  const float* __restrict__ td,
                                                  __half* __restrict__ out) {
    int c = blockIdx.x * 256 + threadIdx.x;
    int ch = blockIdx.y;
    float w = -__expf(td[c]);
    float u = tf[c];
    int idx = ch * DD + c;
    float aa = g_pa[idx], bb = g_pb[idx], pp = g_pp[idx];
    size_t base = (size_t)ch * CL * DD + c;
    for (int i = 0; i < CL; i++) {
        size_t off = base + (size_t)i * DD;
        float kt = k[off], vt = v[off];
        float ww = u + kt;
        float p = fmaxf(pp, ww);
        float e1 = __expf(pp - p), e2 = __expf(ww - p);
        float o = (e1 * aa + e2 * vt) / (e1 * bb + e2);
        out[off] = __float2half_rn(o * r[off]);
        float ww2 = pp + w;
        float p2 = fmaxf(ww2, kt);
        e1 = __expf(ww2 - p2); e2 = __expf(kt - p2);
        aa = e1 * aa + e2 * vt;
        bb = e1 * bb + e2;
        pp = p2;
    }
}

// ---------------- fp16 mma.sync GEMM, 4 warps, 64x64 warp tiles ----------------
// MODE 0: plain  1: sigmoid  2: relu^2 (->half)  3: +aux1  4: *aux1 + aux2
template <int MODE, typename OT>
__global__ __launch_bounds__(128, 2) void gemm_h(
    const __half* __restrict__ A, const __half* __restrict__ W,
    const float* __restrict__ bias,
    const float* __restrict__ aux1, const float* __restrict__ aux2,
    OT* __restrict__ out) {
    extern __shared__ __align__(1024) char smem[];
    const uint32_t sb = saddr(smem);
    const int tid = threadIdx.x;
    const int warp = tid >> 5, lane = tid & 31;
    const int bm = blockIdx.x * BM;
    const int bn = blockIdx.y * BN;
    const int wm = (warp >> 1) * 64;
    const int wn = (warp & 1) * 64;

    // ---- hoisted producer addressing ----
    // per-thread base: row = tid>>3 (16 rows/128thr per 2048B slab), col16 = tid&7
    const uint32_t d0 = SWZ((uint32_t)((tid >> 3) * 128 + (tid & 7) * 16));
    const __half* gA = A + (size_t)bm * DD + (size_t)(tid >> 3) * DD + (tid & 7) * 8;
    const __half* gB = W + (size_t)bn * DD + (size_t)(tid >> 3) * DD + (tid & 7) * 8;

    float acc[4][8][4];
#pragma unroll
    for (int i = 0; i < 4; i++)
#pragma unroll
        for (int j = 0; j < 8; j++)
#pragma unroll
            for (int q = 0; q < 4; q++) acc[i][j][q] = 0.f;

    auto load_stage = [&](int kt) {
        const uint32_t st = sb + (kt % NS) * STAGE_B + d0;
        const int kk = kt * BKH;
#pragma unroll
        for (int i = 0; i < 8; i++) {
            const size_t so = (size_t)(i * 16) * DD + kk;
            cp_async16(st + i * 2048,         gA + so);
            cp_async16(st + 16384 + i * 2048, gB + so);
        }
    };

    load_stage(0); cp_commit();
    load_stage(1); cp_commit();

    // ---- hoisted consumer addressing ----
    const int lrow = lane & 15;
    const uint32_t kxor = (uint32_t)((lane & 7) << 4);
    const uint32_t khi  = (uint32_t)((lane >> 4) * 16);
    uint32_t arow_off[4], brow_off[4];
#pragma unroll
    for (int mi = 0; mi < 4; mi++) arow_off[mi] = (uint32_t)((wm + mi * 16 + lrow) * 128);
#pragma unroll
    for (int g = 0; g < 4; g++) brow_off[g] = (uint32_t)(16384 + (wn + g * 16 + lrow) * 128);

    uint32_t af[2][4][4], bf[2][4][4];
    auto load_frags = [&](const uint32_t st, int ks, int buf) {
        const uint32_t kpart = ((uint32_t)(ks * 32) + khi) ^ kxor;
#pragma unroll
        for (int mi = 0; mi < 4; mi++) ldsm_x4(af[buf][mi], st + arow_off[mi] + kpart);
#pragma unroll
        for (int g = 0; g < 4; g++)   ldsm_x4(bf[buf][g],  st + brow_off[g] + kpart);
    };

    for (int kt = 0; kt < NKT; kt++) {
        cp_wait<1>();
        __syncthreads();                 // single barrier per iteration
        if (kt + 2 < NKT) load_stage(kt + 2);   // writes buf (kt-1)%3: safe post-sync
        cp_commit();

        const uint32_t st = sb + (kt % NS) * STAGE_B;
        load_frags(st, 0, 0);
#pragma unroll
        for (int ks = 0; ks < 4; ks++) {
            const int cur = ks & 1;
            if (ks < 3) load_frags(st, ks + 1, cur ^ 1);
#pragma unroll
            for (int mi = 0; mi < 4; mi++)
#pragma unroll
                for (int g = 0; g < 4; g++) {
                    mma16(acc[mi][2 * g],     af[cur][mi], bf[cur][g][0], bf[cur][g][2]);
                    mma16(acc[mi][2 * g + 1], af[cur][mi], bf[cur][g][1], bf[cur][g][3]);
                }
        }
    }

    // ---------------- epilogue ----------------
    constexpr bool HALF_OUT = (sizeof(OT) == 2);
#pragma unroll
    for (int mi = 0; mi < 4; mi++) {
        const int r0 = bm + wm + mi * 16 + (lane >> 2);
#pragma unroll
        for (int ni = 0; ni < 8; ni++) {
            const int c0 = bn + wn + ni * 8 + (lane & 3) * 2;
            const float b0 = bias[c0], b1 = bias[c0 + 1];
            const size_t i0 = (size_t)r0 * DD + c0;
            const size_t i1 = (size_t)(r0 + 8) * DD + c0;
            float v[4];
            v[0] = acc[mi][ni][0] + b0;
            v[1] = acc[mi][ni][1] + b1;
            v[2] = acc[mi][ni][2] + b0;
            v[3] = acc[mi][ni][3] + b1;
            if (MODE == 1) {
#pragma unroll
                for (int q = 0; q < 4; q++) v[q] = 1.0f / (1.0f + expf(-v[q]));
            } else if (MODE == 2) {
#pragma unroll
                for (int q = 0; q < 4; q++) { float t = v[q] > 0.f ? v[q] : 0.f; v[q] = t * t; }
            } else if (MODE == 3) {
                v[0] += aux1[i0]; v[1] += aux1[i0 + 1];
                v[2] += aux1[i1]; v[3] += aux1[i1 + 1];
            } else if (MODE == 4) {
                v[0] = v[0] * aux1[i0]     + aux2[i0];
                v[1] = v[1] * aux1[i0 + 1] + aux2[i0 + 1];
                v[2] = v[2] * aux1[i1]     + aux2[i1];
                v[3] = v[3] * aux1[i1 + 1] + aux2[i1 + 1];
            }
            if (HALF_OUT) {
                *reinterpret_cast<__half2*>((__half*)out + i0) = __floats2half2_rn(v[0], v[1]);
                *reinterpret_cast<__half2*>((__half*)out + i1) = __floats2half2_rn(v[2], v[3]);
            } else {
                float* o = (float*)out;
                o[i0] = v[0]; o[i0 + 1] = v[1];
                o[i1] = v[2]; o[i1 + 1] = v[3];
            }
        }
    }
}

// ---------------- host orchestration ----------------
extern "C" void kernel_launch(void* const* d_in, const int* in_sizes, int n_in,
                              void* d_out, int out_size) {
    const float* x = (const float*)d_in[0];
    const float* w_src[7];
    const float* b_src[7];
    for (int i = 0; i < 7; i++) {
        w_src[i] = (const float*)d_in[1 + 2 * i];
        b_src[i] = (const float*)d_in[2 + 2 * i];
    }
    const float* ln1g = (const float*)d_in[15];
    const float* ln1b = (const float*)d_in[16];
    const float* ln2g = (const float*)d_in[17];
    const float* ln2b = (const float*)d_in[18];
    const float* mixk = (const float*)d_in[19];
    const float* mixv = (const float*)d_in[20];
    const float* mixr = (const float*)d_in[21];
    const float* fmk  = (const float*)d_in[22];
    const float* fmr  = (const float*)d_in[23];
    const float* tf   = (const float*)d_in[24];
    const float* td   = (const float*)d_in[25];
    float* out = (float*)d_out;

    __half *p_xyh, *p_h0, *p_h1, *p_h2, *p_t0h, *p_wh;
    float *p_k, *p_v, *p_r, *p_rz;
    cudaGetSymbolAddress((void**)&p_xyh, g_xyh);
    cudaGetSymbolAddress((void**)&p_h0,  g_h0);
    cudaGetSymbolAddress((void**)&p_h1,  g_h1);
    cudaGetSymbolAddress((void**)&p_h2,  g_h2);
    cudaGetSymbolAddress((void**)&p_t0h, g_t0h);
    cudaGetSymbolAddress((void**)&p_wh,  g_wh);
    cudaGetSymbolAddress((void**)&p_k,   g_k);
    cudaGetSymbolAddress((void**)&p_v,   g_v);
    cudaGetSymbolAddress((void**)&p_r,   g_r);
    cudaGetSymbolAddress((void**)&p_rz,  g_rz);

    cudaFuncSetAttribute(gemm_h<0, float>,  cudaFuncAttributeMaxDynamicSharedMemorySize, SMEM_DYN);
    cudaFuncSetAttribute(gemm_h<1, float>,  cudaFuncAttributeMaxDynamicSharedMemorySize, SMEM_DYN);
    cudaFuncSetAttribute(gemm_h<2, __half>, cudaFuncAttributeMaxDynamicSharedMemorySize, SMEM_DYN);
    cudaFuncSetAttribute(gemm_h<3, float>,  cudaFuncAttributeMaxDynamicSharedMemorySize, SMEM_DYN);
    cudaFuncSetAttribute(gemm_h<4, float>,  cudaFuncAttributeMaxDynamicSharedMemorySize, SMEM_DYN);

    const int nwc = 7 * (DD * DD / 4) / 256;
    wconv7_kernel<<<nwc, 256>>>((const float4*)w_src[0], (const float4*)w_src[1],
                                (const float4*)w_src[2], (const float4*)w_src[3],
                                (const float4*)w_src[4], (const float4*)w_src[5],
                                (const float4*)w_src[6], (__half2*)p_wh);

    const int nmix = TT * DD / 2 / 256;
    dim3 gg(TT / BM, DD / BN);   // (64, 16)
    dim3 gwkv(DD / 256, NCH);

    // --- attention branch ---
    ln_kernel<<<TT, 256>>>(x, ln1g, ln1b, p_xyh);
    mixn_kernel<3><<<nmix, 256>>>((const __half2*)p_xyh,
                                  (const float2*)mixk, (const float2*)mixv, (const float2*)mixr,
                                  (__half2*)p_h0, (__half2*)p_h1, (__half2*)p_h2);

    gemm_h<0, float><<<gg, 128, SMEM_DYN>>>(p_h0, p_wh + 0 * (size_t)DD * DD, b_src[0], nullptr, nullptr, p_k);
    gemm_h<0, float><<<gg, 128, SMEM_DYN>>>(p_h1, p_wh + 1 * (size_t)DD * DD, b_src[1], nullptr, nullptr, p_v);
    gemm_h<1, float><<<gg, 128, SMEM_DYN>>>(p_h2, p_wh + 2 * (size_t)DD * DD, b_src[2], nullptr, nullptr, p_r);

    wkv_phase1<<<gwkv, 256>>>(p_k, p_v, td);
    wkv_phase2<<<DD / 256, 256>>>(td);
    wkv_phase3<<<gwkv, 256>>>(p_k, p_v, p_r, tf, td, p_t0h);

    gemm_h<3, float><<<gg, 128, SMEM_DYN>>>(p_t0h, p_wh + 3 * (size_t)DD * DD, b_src[3], x, nullptr, p_rz);

    // --- FFN branch ---
    ln_kernel<<<TT, 256>>>(p_rz, ln2g, ln2b, p_xyh);
    mixn_kernel<2><<<nmix, 256>>>((const __half2*)p_xyh,
                                  (const float2*)fmr, (const float2*)fmk, nullptr,
                                  (__half2*)p_h0, (__half2*)p_h1, nullptr);

    gemm_h<1, float><<<gg, 128, SMEM_DYN>>>(p_h0, p_wh + 6 * (size_t)DD * DD, b_src[6], nullptr, nullptr, p_r);
    gemm_h<2, __half><<<gg, 128, SMEM_DYN>>>(p_h1, p_wh + 4 * (size_t)DD * DD, b_src[4], nullptr, nullptr, p_t0h);
    gemm_h<4, float><<<gg, 128, SMEM_DYN>>>(p_t0h, p_wh + 5 * (size_t)DD * DD, b_src[5], p_r, p_rz, out);
}